// round 11
// baseline (speedup 1.0000x reference)
#include <cuda_runtime.h>
#include <cuda_fp16.h>

// Problem constants
#define NB 16            // batch B
#define TT 12            // T_IN
#define TO 24            // T_TOTAL
#define NN 5000          // nodes
#define CC 4             // channels
#define KK 16            // neighbors
#define HH 4             // heads
#define BT (NB * TT)     // 192
#define DIN (TT * HH)    // 48
#define DOUT (TO - TT)   // 12
#define NT 2             // nodes per block
#define THREADS 384
#define A_STRIDE 56      // halves per A row (112B = 7*16B -> conflict-free ldmatrix)

typedef unsigned long long u64;

// Scratch: x transposed+converted to fp16: [N][bt] = (c01,c23). 7.68 MB, L2-resident.
__device__ uint2 g_xt2[NN * BT];

static __device__ __forceinline__ float2 h2f(unsigned u) {
    __half2 h = *reinterpret_cast<__half2*>(&u);
    return __half22float2(h);
}
static __device__ __forceinline__ u64 pk(float lo, float hi) {
    u64 r;
    asm("mov.b64 %0, {%1, %2};" : "=l"(r) : "f"(lo), "f"(hi));
    return r;
}
static __device__ __forceinline__ u64 pkh(unsigned u) {   // fp16x2 -> packed f32x2
    float2 f = h2f(u);
    return pk(f.x, f.y);
}
static __device__ __forceinline__ u64 fma2(u64 a, u64 b, u64 c) {
    u64 d;
    asm("fma.rn.f32x2 %0, %1, %2, %3;" : "=l"(d) : "l"(a), "l"(b), "l"(c));
    return d;
}
static __device__ __forceinline__ float2 upk(u64 v) {
    float2 f;
    asm("mov.b64 {%0, %1}, %2;" : "=f"(f.x), "=f"(f.y) : "l"(v));
    return f;
}
static __device__ __forceinline__ unsigned sm32(const void* p) {
    return (unsigned)__cvta_generic_to_shared(p);
}

// ---------------------------------------------------------------------------
// Kernel 1: x [B,T,N,C] f32 -> g_xt2 [N][bt] fp16 (transposed)  AND out[:, :12] = x
// ---------------------------------------------------------------------------
__global__ void __launch_bounds__(1024) transpose_convert_kernel(
    const float* __restrict__ x, float* __restrict__ out)
{
    __shared__ uint2 tile[32][33];
    const float4* __restrict__ x4 = (const float4*)x;
    float4* __restrict__ out4 = (float4*)out;

    int tx = threadIdx.x, ty = threadIdx.y;
    int n  = blockIdx.x * 32 + tx;
    int bt = blockIdx.y * 32 + ty;          // gridDim.y*32 == 192 exactly

    if (n < NN) {
        float4 v = x4[bt * NN + n];
        __half2 h01 = __floats2half2_rn(v.x, v.y);
        __half2 h23 = __floats2half2_rn(v.z, v.w);
        uint2 u;
        u.x = *reinterpret_cast<unsigned*>(&h01);
        u.y = *reinterpret_cast<unsigned*>(&h23);
        tile[ty][tx] = u;
        int b = bt / TT, t = bt - b * TT;
        out4[(b * TO + t) * NN + n] = v;    // out[:, :12] = x (coalesced)
    }
    __syncthreads();

    int n2  = blockIdx.x * 32 + ty;
    int bt2 = blockIdx.y * 32 + tx;
    if (n2 < NN) {
        g_xt2[n2 * BT + bt2] = tile[tx][ty];   // 256B/warp coalesced
    }
}

// ---------------------------------------------------------------------------
// Kernel 2: per node-pair, 384 threads.
//   phase 1: thread = (nl, bt): fp16 uint2 gather + f32x2 agg -> fp16 A tile
//   phase 2: warps 0-7, one m16-tile each: D[128,12] = A[128,48] @ W[48,12]
//            via mma.m16n8k16 (f32 acc); bias+ReLU; staged coalesced stores
// ---------------------------------------------------------------------------
__global__ void __launch_bounds__(THREADS, 4) gnn_main_kernel(
    const float* __restrict__ dists, const int* __restrict__ neighbors,
    const float* __restrict__ W, const float* __restrict__ bias,
    float* __restrict__ out)
{
    __shared__ __align__(16) __half A_s[128 * A_STRIDE];   // rows r=nl*64+b*4+c, cols t*4+h
    __shared__ __align__(16) __half WT_s[16 * A_STRIDE];   // rows o, cols th; rows 12-15 unused
    __shared__ ulonglong2 wp_s[NT][KK][2];                  // packed gaussian weights
    __shared__ int   nbr_s[NT][KK];
    __shared__ float b_s[DOUT];
    __shared__ __align__(16) float ys2[384 * 4];            // [(b*12+o)*2+nl][c]

    const int tid = threadIdx.x;              // 0..383
    const int n0  = blockIdx.x * NT;

    // --- Phase 0 ---
    if (tid < NT * KK) {
        int nn = tid >> 4, k = tid & 15;
        float d = dists[(n0 + nn) * KK + k];
        nbr_s[nn][k] = neighbors[(n0 + nn) * KK + k];
        float p = d * d * (1.0f / 36.0f);     // d^2 / sigma^2
        float w0 = __expf(-0.25f * p);
        float w1 = __expf(-0.50f * p);
        float w2 = __expf(-0.75f * p);
        float w3 = __expf(-p);
        wp_s[nn][k][0] = make_ulonglong2(pk(w0, w0), pk(w1, w1));
        wp_s[nn][k][1] = make_ulonglong2(pk(w2, w2), pk(w3, w3));
    }
    #pragma unroll
    for (int i = tid; i < DIN * DOUT; i += THREADS) {
        int th = i / DOUT, o = i - th * DOUT;
        WT_s[o * A_STRIDE + th] = __float2half(W[i]);      // W^T, fp16
    }
    if (tid < DOUT) b_s[tid] = bias[tid];
    __syncthreads();

    // --- Phase 1: fp16 gather (uint2/thread) + packed weighted agg -> fp16 A ---
    {
        const int nl = tid / BT;                 // 0..1, warp-uniform (192 = 6 warps)
        const int bt = tid - nl * BT;
        const int b  = bt / TT, t = bt - b * TT;

        u64 acc[HH][2];                          // [h][c01|c23]
        #pragma unroll
        for (int h = 0; h < HH; ++h) { acc[h][0] = 0ULL; acc[h][1] = 0ULL; }

        #pragma unroll
        for (int k = 0; k < KK; ++k) {
            uint2 v = g_xt2[nbr_s[nl][k] * BT + bt];   // 256B/warp coalesced
            u64 x01 = pkh(v.x);                  // c0,c1
            u64 x23 = pkh(v.y);                  // c2,c3
            ulonglong2 wA = wp_s[nl][k][0];      // (w0,w0),(w1,w1)
            ulonglong2 wB = wp_s[nl][k][1];      // (w2,w2),(w3,w3)
            acc[0][0] = fma2(x01, wA.x, acc[0][0]);
            acc[0][1] = fma2(x23, wA.x, acc[0][1]);
            acc[1][0] = fma2(x01, wA.y, acc[1][0]);
            acc[1][1] = fma2(x23, wA.y, acc[1][1]);
            acc[2][0] = fma2(x01, wB.x, acc[2][0]);
            acc[2][1] = fma2(x23, wB.x, acc[2][1]);
            acc[3][0] = fma2(x01, wB.y, acc[3][0]);
            acc[3][1] = fma2(x23, wB.y, acc[3][1]);
        }

        // Convert to fp16: A[row = nl*64+b*4+c][col = t*4+h]
        float v[HH][CC];
        #pragma unroll
        for (int h = 0; h < HH; ++h) {
            float2 pA = upk(acc[h][0]);
            float2 pB = upk(acc[h][1]);
            v[h][0] = pA.x; v[h][1] = pA.y; v[h][2] = pB.x; v[h][3] = pB.y;
        }
        const int rowbase = nl * 64 + b * 4;
        #pragma unroll
        for (int c = 0; c < CC; ++c) {
            __half2 lo2 = __floats2half2_rn(v[0][c], v[1][c]);
            __half2 hi2 = __floats2half2_rn(v[2][c], v[3][c]);
            uint2 u;
            u.x = *reinterpret_cast<unsigned*>(&lo2);
            u.y = *reinterpret_cast<unsigned*>(&hi2);
            *(uint2*)&A_s[(rowbase + c) * A_STRIDE + t * 4] = u;
        }
    }
    __syncthreads();

    // --- Phase 2: tensor-core matmul. Warps 0-7 own one m16-tile each. ---
    {
        const int w    = tid >> 5;                // 0..11
        const int lane = tid & 31;
        const int gID  = lane >> 2;
        const int tig  = lane & 3;

        if (w < 8) {
            // B fragments: W^T[n][k] col-major pairs.
            unsigned bf[2][3][2];
            #pragma unroll
            for (int nt = 0; nt < 2; ++nt)
                #pragma unroll
                for (int s = 0; s < 3; ++s) {
                    int n = nt * 8 + gID;
                    bf[nt][s][0] = *(const unsigned*)&WT_s[n * A_STRIDE + s * 16 + tig * 2];
                    bf[nt][s][1] = *(const unsigned*)&WT_s[n * A_STRIDE + s * 16 + tig * 2 + 8];
                }

            float d0[4] = {0.f, 0.f, 0.f, 0.f};
            float d1[4] = {0.f, 0.f, 0.f, 0.f};

            unsigned abase = sm32(A_s) +
                (w * 16 + (lane & 15)) * (A_STRIDE * 2) + (lane >> 4) * 16;
            #pragma unroll
            for (int s = 0; s < 3; ++s) {
                unsigned a0, a1, a2, a3;
                asm volatile(
                    "ldmatrix.sync.aligned.m8n8.x4.shared.b16 {%0,%1,%2,%3}, [%4];"
                    : "=r"(a0), "=r"(a1), "=r"(a2), "=r"(a3)
                    : "r"(abase + s * 32));
                asm volatile(
                    "mma.sync.aligned.m16n8k16.row.col.f32.f16.f16.f32 "
                    "{%0,%1,%2,%3}, {%4,%5,%6,%7}, {%8,%9}, {%0,%1,%2,%3};"
                    : "+f"(d0[0]), "+f"(d0[1]), "+f"(d0[2]), "+f"(d0[3])
                    : "r"(a0), "r"(a1), "r"(a2), "r"(a3),
                      "r"(bf[0][s][0]), "r"(bf[0][s][1]));
                asm volatile(
                    "mma.sync.aligned.m16n8k16.row.col.f32.f16.f16.f32 "
                    "{%0,%1,%2,%3}, {%4,%5,%6,%7}, {%8,%9}, {%0,%1,%2,%3};"
                    : "+f"(d1[0]), "+f"(d1[1]), "+f"(d1[2]), "+f"(d1[3])
                    : "r"(a0), "r"(a1), "r"(a2), "r"(a3),
                      "r"(bf[1][s][0]), "r"(bf[1][s][1]));
            }

            // Epilogue: bias + ReLU, stage to ys2.
            #pragma unroll
            for (int nt = 0; nt < 2; ++nt) {
                const float* dd = nt ? d1 : d0;
                #pragma unroll
                for (int i = 0; i < 4; ++i) {
                    int o = nt * 8 + tig * 2 + (i & 1);
                    if (o < DOUT) {
                        int row = w * 16 + gID + (i >> 1) * 8;   // nl*64 + b*4 + c
                        int nl2 = row >> 6, bb = (row >> 2) & 15, cc = row & 3;
                        float val = fmaxf(dd[i] + b_s[o], 0.f);
                        ys2[(((bb * DOUT + o) << 1) + nl2) * 4 + cc] = val;
                    }
                }
            }
        }
    }
    __syncthreads();

    // --- Coalesced float4 stores: 384 cells / 384 threads = 1 each ---
    {
        float4* __restrict__ out4 = (float4*)out;
        int cell = tid >> 1, j = tid & 1;        // cell = b*12+o, j = node
        int bb = cell / DOUT, oo = cell - bb * DOUT;
        float4 v = *(const float4*)&ys2[tid * 4];
        out4[(bb * TO + TT + oo) * NN + n0 + j] = v;
    }
}

// ---------------------------------------------------------------------------
// metadata order: x (f32), dists (f32), W (f32), b (f32), neighbors (i32);
// output f32 (7680000)
// ---------------------------------------------------------------------------
extern "C" void kernel_launch(void* const* d_in, const int* in_sizes, int n_in,
                              void* d_out, int out_size)
{
    const float* x         = (const float*)d_in[0];
    const float* dists     = (const float*)d_in[1];
    const float* W         = (const float*)d_in[2];
    const float* bias      = (const float*)d_in[3];
    const int*   neighbors = (const int*)d_in[4];
    float* out = (float*)d_out;

    dim3 tb(32, 32);
    dim3 tg((NN + 31) / 32, BT / 32);        // 157 x 6
    transpose_convert_kernel<<<tg, tb>>>(x, out);

    gnn_main_kernel<<<NN / NT, THREADS>>>(dists, neighbors, W, bias, out);
}